// round 5
// baseline (speedup 1.0000x reference)
#include <cuda_runtime.h>
#include <cuda_fp16.h>
#include <stdint.h>

// StackedUnidirLSTMDecoder: B=64, L=4, H=1024, T=128
#define BB    64
#define LL    4
#define HH    1024
#define TT    128
#define GG    4096
#define NCTA  128
#define NTHR  512             // 16 warps: (ks 0..3) x (wm 0..3)

// ---------------------------------------------------------------------------
// Device-global scratch
// ---------------------------------------------------------------------------
// W packed in mma B-fragment order (fp16):
// [L][NCTA][kt=128][np=2][lane=32][8 halfs]; per-CTA slice = 128KB/layer
__device__ __half g_Wp[(size_t)LL * NCTA * 128 * 512];

// Activations packed as A-fragment blocks:
// g_A[p][l][mt=4][kt=128][lane=32][4xu32]; kt 0..63 = X(layer input), 64..127 = H
//   u32 reg order per lane: {a0,a1,a2,a3} = (rlo,klo),(rhi,klo),(rlo,khi),(rhi,khi)
__device__ __half g_A[2][LL][4 * 128 * 256];
__device__ float  g_bias[LL * GG];            // b_ih + b_hh precombined
__device__ unsigned g_bar_cnt;
__device__ unsigned g_bar_gen;

// ---------------------------------------------------------------------------
// Prologue 1: pack W_ih|W_hh (fp32 [L][4H][H] each) into fragment order fp16
// ---------------------------------------------------------------------------
__global__ void pack_weights(const float* __restrict__ Wih,
                             const float* __restrict__ Whh) {
    int tid = blockIdx.x * blockDim.x + threadIdx.x;
    if (tid >= LL * NCTA * 128 * 32) return;
    int lane = tid & 31;
    int kt   = (tid >> 5) & 127;
    int cta  = (tid >> 12) & 127;
    int l    = tid >> 19;
    int c8 = lane >> 2;
    int kq = (lane & 3) * 2;

    #pragma unroll
    for (int np = 0; np < 2; np++) {
        #pragma unroll
        for (int ntl = 0; ntl < 2; ntl++) {
            int nt = np * 2 + ntl;
            int n  = nt * 1024 + cta * 8 + c8;
            __half v[4];
            #pragma unroll
            for (int e = 0; e < 4; e++) {
                int k = kt * 16 + kq + (e & 1) + 8 * (e >> 1);
                float w = (k < HH) ? Wih[((size_t)l * GG + n) * HH + k]
                                   : Whh[((size_t)l * GG + n) * HH + (k - HH)];
                v[e] = __float2half(w);
            }
            size_t off = ((((size_t)(l * NCTA + cta) * 128 + kt) * 2 + np) * 32
                          + lane) * 8 + ntl * 4;
            *(uint2*)&g_Wp[off] = *(uint2*)v;
        }
    }
}

// ---------------------------------------------------------------------------
// Prologue 2: init A (x, h0) into fragment layout; precombine biases
// ---------------------------------------------------------------------------
__global__ void init_state(const float* __restrict__ x,
                           const float* __restrict__ h0,
                           const float* __restrict__ b_ih,
                           const float* __restrict__ b_hh) {
    int i = blockIdx.x * blockDim.x + threadIdx.x;
    if (i < LL * GG) g_bias[i] = b_ih[i] + b_hh[i];
    if (i >= LL * BB * HH) return;
    int k = i & (HH - 1);
    int r = (i >> 10) & (BB - 1);
    int l = i >> 16;

    int mt   = r >> 4;
    int lane = (r & 7) * 4 + ((k & 7) >> 1);
    int reg  = ((r & 15) >> 3) + 2 * ((k & 15) >> 3);
    // halfs offset inside [mt][kt] block of 256 halfs:
    int inblk = lane * 8 + reg * 2 + (k & 1);

    // h0 -> H part (kt = 64 + k/16), parity 0
    g_A[0][l][(mt * 128 + 64 + (k >> 4)) * 256 + inblk] = __float2half(h0[i]);
    // x  -> X part of layer 0, parity 0
    if (l == 0)
        g_A[0][0][(mt * 128 + (k >> 4)) * 256 + inblk] = __float2half(x[r * HH + k]);
}

// ---------------------------------------------------------------------------
// Grid barrier: acq_rel arrive, release flip, acquire poll. 128 CTAs resident.
// ---------------------------------------------------------------------------
__device__ __forceinline__ void grid_sync() {
    __syncthreads();
    if (threadIdx.x == 0) {
        unsigned gen;
        asm volatile("ld.acquire.gpu.global.u32 %0, [%1];"
                     : "=r"(gen) : "l"(&g_bar_gen));
        unsigned prev;
        asm volatile("atom.acq_rel.gpu.global.add.u32 %0, [%1], 1;"
                     : "=r"(prev) : "l"(&g_bar_cnt));
        if (prev == NCTA - 1) {
            asm volatile("st.relaxed.gpu.global.u32 [%0], %1;"
                         :: "l"(&g_bar_cnt), "r"(0u));
            asm volatile("st.release.gpu.global.u32 [%0], %1;"
                         :: "l"(&g_bar_gen), "r"(gen + 1u));
        } else {
            unsigned cur;
            do {
                asm volatile("ld.acquire.gpu.global.u32 %0, [%1];"
                             : "=r"(cur) : "l"(&g_bar_gen));
            } while (cur == gen);
        }
    }
    __syncthreads();
}

__device__ __forceinline__ void mma16816(float* d,
                                         unsigned a0, unsigned a1, unsigned a2, unsigned a3,
                                         unsigned b0, unsigned b1) {
    asm volatile(
        "mma.sync.aligned.m16n8k16.row.col.f32.f16.f16.f32 "
        "{%0,%1,%2,%3},{%4,%5,%6,%7},{%8,%9},{%0,%1,%2,%3};\n"
        : "+f"(d[0]), "+f"(d[1]), "+f"(d[2]), "+f"(d[3])
        : "r"(a0), "r"(a1), "r"(a2), "r"(a3), "r"(b0), "r"(b1));
}

__device__ __forceinline__ float sigm(float v) { return 1.0f / (1.0f + __expf(-v)); }
__device__ __forceinline__ float tanh_fast(float v) {
    return 2.0f / (1.0f + __expf(-2.0f * v)) - 1.0f;
}

// ---------------------------------------------------------------------------
// Persistent LSTM. CTA c owns gate cols {g*1024+j : j in [8c,8c+8)}.
// Warp (ks, wm): m-tile wm, k-tiles [32ks, 32ks+32). ks=1..3 deposit partials
// to SMEM; ks=0 combines and does the register-resident cell update.
// ---------------------------------------------------------------------------
__global__ void __launch_bounds__(NTHR, 1)
lstm_persistent(const float* __restrict__ c0,
                float* __restrict__ out) {
    const int cta  = blockIdx.x;
    const int w    = threadIdx.x >> 5;
    const int lane = threadIdx.x & 31;
    const int ks   = w >> 2;
    const int wm   = w & 3;
    const int qrow = lane >> 2;
    const int tq   = lane & 3;

    __shared__ float s_part[3][4][16][32];   // [ks-1][wm][acc idx][lane]

    // ks==0 threads own cell state for (r = wm*16+qrow(+8), j = cta*8+tq*2(+1))
    float creg[LL][4];
    if (ks == 0) {
        #pragma unroll
        for (int l = 0; l < LL; l++)
            #pragma unroll
            for (int hh2 = 0; hh2 < 2; hh2++)
                #pragma unroll
                for (int u = 0; u < 2; u++) {
                    int r = wm * 16 + qrow + hh2 * 8;
                    int j = cta * 8 + tq * 2 + u;
                    creg[l][hh2 * 2 + u] = c0[((size_t)l * BB + r) * HH + j];
                }
    }

    const char* __restrict__ Wcta =
        (const char*)g_Wp + (size_t)cta * 128 * 1024;   // this CTA's slice, layer 0

    for (int t = 0; t < TT; t++) {
        const int p = t & 1;
        #pragma unroll
        for (int l = 0; l < LL; l++) {
            // A stream: [mt=wm][kt = 32ks .. 32ks+32) blocks of 512B
            const char* Ab = (const char*)g_A[p][l]
                           + (size_t)(wm * 128 + ks * 32) * 512 + lane * 16;
            const char* Wb = Wcta + (size_t)(l * NCTA) * 131072
                           + (size_t)(ks * 32) * 1024 + lane * 16;

            float acc[4][4];
            #pragma unroll
            for (int a = 0; a < 4; a++)
                #pragma unroll
                for (int b = 0; b < 4; b++) acc[a][b] = 0.0f;

            #pragma unroll 4
            for (int kk = 0; kk < 32; kk++) {
                uint4 a   = __ldcg((const uint4*)(Ab + (size_t)kk * 512));
                uint4 w01 = *(const uint4*)(Wb + (size_t)kk * 1024);
                uint4 w23 = *(const uint4*)(Wb + (size_t)kk * 1024 + 512);
                mma16816(acc[0], a.x, a.y, a.z, a.w, w01.x, w01.y);
                mma16816(acc[1], a.x, a.y, a.z, a.w, w01.z, w01.w);
                mma16816(acc[2], a.x, a.y, a.z, a.w, w23.x, w23.y);
                mma16816(acc[3], a.x, a.y, a.z, a.w, w23.z, w23.w);
            }

            if (ks != 0) {
                #pragma unroll
                for (int g = 0; g < 4; g++)
                    #pragma unroll
                    for (int ci = 0; ci < 4; ci++)
                        s_part[ks - 1][wm][g * 4 + ci][lane] = acc[g][ci];
            }
            __syncthreads();

            if (ks == 0) {
                #pragma unroll
                for (int g = 0; g < 4; g++)
                    #pragma unroll
                    for (int ci = 0; ci < 4; ci++)
                        acc[g][ci] += s_part[0][wm][g * 4 + ci][lane]
                                    + s_part[1][wm][g * 4 + ci][lane]
                                    + s_part[2][wm][g * 4 + ci][lane];

                // destinations (fragment-layout u32 stores, own lane)
                char* dstH = (char*)g_A[p ^ 1][l];
                char* dstX = (l < LL - 1) ? (char*)g_A[p][l + 1]
                                          : (char*)g_A[p ^ 1][0];  // y feedback
                int blkH = wm * 128 + 64 + (cta >> 1);
                int blkX = wm * 128 + (cta >> 1);
                int lobytes = lane * 16 + 4 * 2 * (cta & 1);

                const float* __restrict__ bl = g_bias + l * GG;
                int j0 = cta * 8 + tq * 2;

                #pragma unroll
                for (int hh2 = 0; hh2 < 2; hh2++) {
                    int r = wm * 16 + qrow + hh2 * 8;
                    float hn2[2];
                    #pragma unroll
                    for (int u = 0; u < 2; u++) {
                        int j  = j0 + u;
                        int ci = hh2 * 2 + u;
                        float gi = acc[0][ci] + bl[j];
                        float gf = acc[1][ci] + bl[1024 + j];
                        float gg = acc[2][ci] + bl[2048 + j];
                        float go = acc[3][ci] + bl[3072 + j];
                        float ig = sigm(gi), fg = sigm(gf), og = sigm(go);
                        float gt = tanh_fast(gg);
                        float cn = fg * creg[l][ci] + ig * gt;
                        creg[l][ci] = cn;
                        hn2[u] = og * tanh_fast(cn);
                    }
                    unsigned hv = (unsigned)__half_as_ushort(__float2half(hn2[0]))
                                | ((unsigned)__half_as_ushort(__float2half(hn2[1])) << 16);
                    *(unsigned*)(dstH + (size_t)blkH * 512 + lobytes + hh2 * 4) = hv;
                    *(unsigned*)(dstX + (size_t)blkX * 512 + lobytes + hh2 * 4) = hv;
                    if (l == LL - 1)
                        *(float2*)&out[((size_t)r * TT + t) * HH + j0] =
                            make_float2(hn2[0], hn2[1]);
                }
            }
            grid_sync();
        }
    }
}

// ---------------------------------------------------------------------------
// kernel_launch: pack -> init -> persistent run (graph-capturable)
// inputs: x, h0, c0, W_ih, W_hh, b_ih, b_hh, seq_len
// ---------------------------------------------------------------------------
extern "C" void kernel_launch(void* const* d_in, const int* in_sizes, int n_in,
                              void* d_out, int out_size) {
    const float* x   = (const float*)d_in[0];
    const float* h0  = (const float*)d_in[1];
    const float* c0  = (const float*)d_in[2];
    const float* Wih = (const float*)d_in[3];
    const float* Whh = (const float*)d_in[4];
    const float* bih = (const float*)d_in[5];
    const float* bhh = (const float*)d_in[6];
    float* out = (float*)d_out;

    pack_weights<<<(LL * NCTA * 128 * 32) / 256, 256>>>(Wih, Whh);
    init_state<<<(LL * BB * HH + 255) / 256, 256>>>(x, h0, bih, bhh);
    lstm_persistent<<<NCTA, NTHR>>>(c0, out);
}